// round 1
// baseline (speedup 1.0000x reference)
#include <cuda_runtime.h>

#define N_EMBD 2048
#define NHEAD  16
#define HD     128
#define BATCH  2
#define TSEQ   2048
#define MTOT   (BATCH * TSEQ)      // 4096
#define KDIM   N_EMBD              // 2048
#define NKV    (2 * HD)            // 256
#define NTOT   (NKV + N_EMBD)      // 2304

// Scratch (allocation-free rule: __device__ globals)
__device__ float g_q [MTOT * N_EMBD];   // 32 MB
__device__ float g_kv[MTOT * NKV];      // 4 MB

// ---------------------------------------------------------------------------
// Fused SGEMM:  C = X[4096,2048] @ W^T, where W = concat(w_kv[256,2048], w_q[2048,2048])
// Tile 128x128x8, 256 threads, 8x8 micro-tile per thread.
// ---------------------------------------------------------------------------
__global__ __launch_bounds__(256, 2)
void gemm_fused(const float* __restrict__ x,
                const float* __restrict__ w_kv,
                const float* __restrict__ w_q) {
    __shared__ float As[8][128];
    __shared__ float Bs[8][128];

    const int n0 = blockIdx.x * 128;
    const int m0 = blockIdx.y * 128;

    const float* Bmat;
    float* C;
    int ldc;
    if (n0 < NKV) { Bmat = w_kv + n0 * KDIM;          C = g_kv + n0;          ldc = NKV;    }
    else          { Bmat = w_q  + (n0 - NKV) * KDIM;  C = g_q  + (n0 - NKV);  ldc = N_EMBD; }

    const int tid  = threadIdx.x;
    const int lrow = tid >> 1;            // 0..127
    const int seg  = (tid & 1) * 4;       // 0 or 4
    const int tx   = tid & 15;
    const int ty   = tid >> 4;

    const float* Ap = x    + (m0 + lrow) * KDIM + seg;
    const float* Bp = Bmat + lrow * KDIM + seg;

    float acc[8][8];
#pragma unroll
    for (int i = 0; i < 8; i++)
#pragma unroll
        for (int j = 0; j < 8; j++) acc[i][j] = 0.f;

    for (int k0 = 0; k0 < KDIM; k0 += 8) {
        float4 av = *(const float4*)(Ap + k0);
        float4 bv = *(const float4*)(Bp + k0);
        As[seg + 0][lrow] = av.x; As[seg + 1][lrow] = av.y;
        As[seg + 2][lrow] = av.z; As[seg + 3][lrow] = av.w;
        Bs[seg + 0][lrow] = bv.x; Bs[seg + 1][lrow] = bv.y;
        Bs[seg + 2][lrow] = bv.z; Bs[seg + 3][lrow] = bv.w;
        __syncthreads();
#pragma unroll
        for (int kk = 0; kk < 8; kk++) {
            float a[8], b[8];
            *(float4*)&a[0] = *(const float4*)&As[kk][ty * 8];
            *(float4*)&a[4] = *(const float4*)&As[kk][ty * 8 + 4];
            *(float4*)&b[0] = *(const float4*)&Bs[kk][tx * 8];
            *(float4*)&b[4] = *(const float4*)&Bs[kk][tx * 8 + 4];
#pragma unroll
            for (int i = 0; i < 8; i++)
#pragma unroll
                for (int j = 0; j < 8; j++)
                    acc[i][j] += a[i] * b[j];
        }
        __syncthreads();
    }

#pragma unroll
    for (int i = 0; i < 8; i++) {
        float* Crow = C + (m0 + ty * 8 + i) * ldc + tx * 8;
        *(float4*)&Crow[0] = make_float4(acc[i][0], acc[i][1], acc[i][2], acc[i][3]);
        *(float4*)&Crow[4] = make_float4(acc[i][4], acc[i][5], acc[i][6], acc[i][7]);
    }
}

// ---------------------------------------------------------------------------
// Flash attention fp32, causal. BM=BN=64, D=128, 256 threads (16x16 grid),
// strided 4x4 score micro-tiles (rows ty+16r, cols tx+16c) for conflict-free
// smem reads. K transposed to [d][n] in smem (stride 65), V kept [n][d]
// (stride 132, float4-aligned). Online softmax via shfl over 16-lane groups.
// ---------------------------------------------------------------------------
#define BM 64
#define BN 64
#define KSTR 65               // [d][n] stride
#define VSTR 132              // [n][d] stride (132*4 = 16B-aligned)
#define QS_SIZE (128 * KSTR)  // 8320 floats
#define KV_SIZE (BN * VSTR)   // 8448 floats (>= 128*KSTR would be 8320; K fits)
#define PS_STR  65
#define SMEM_FLOATS (QS_SIZE + KV_SIZE + BM * PS_STR)
#define SMEM_BYTES  (SMEM_FLOATS * 4)

__global__ __launch_bounds__(256, 1)
void flash_attn(float* __restrict__ out) {
    extern __shared__ float sm[];
    float* Qs = sm;                      // [d][m], stride KSTR
    float* KV = sm + QS_SIZE;            // K: [d][n] stride KSTR  |  V: [n][d] stride VSTR
    float* Ps = sm + QS_SIZE + KV_SIZE;  // [m][n], stride PS_STR

    const int tid = threadIdx.x;
    const int tx  = tid & 15;
    const int ty  = tid >> 4;
    const int mtile = gridDim.x - 1 - blockIdx.x;   // big blocks first
    const int qm0 = mtile * BM;
    const int b   = blockIdx.y >> 4;
    const int h   = blockIdx.y & 15;
    const int xbase = b * TSEQ;
    const float scale = 0.08838834764831845f;       // 1/sqrt(128)

    // Load Q tile (scaled), transpose to [d][m]
#pragma unroll
    for (int i = 0; i < 8; i++) {
        int lin = tid + 256 * i;
        int row = lin >> 5;
        int d4  = (lin & 31) * 4;
        float4 v = *(const float4*)&g_q[(xbase + qm0 + row) * N_EMBD + h * HD + d4];
        Qs[(d4 + 0) * KSTR + row] = v.x * scale;
        Qs[(d4 + 1) * KSTR + row] = v.y * scale;
        Qs[(d4 + 2) * KSTR + row] = v.z * scale;
        Qs[(d4 + 3) * KSTR + row] = v.w * scale;
    }

    float m_i[4], l_i[4], acc[4][8];
#pragma unroll
    for (int r = 0; r < 4; r++) {
        m_i[r] = -1e30f; l_i[r] = 0.f;
#pragma unroll
        for (int u = 0; u < 8; u++) acc[r][u] = 0.f;
    }

    for (int n0 = 0; n0 <= qm0; n0 += BN) {
        // K tile -> KV transposed [d][n]
#pragma unroll
        for (int i = 0; i < 8; i++) {
            int lin = tid + 256 * i;
            int row = lin >> 5;
            int d4  = (lin & 31) * 4;
            float4 v = *(const float4*)&g_kv[(xbase + n0 + row) * NKV + d4];
            KV[(d4 + 0) * KSTR + row] = v.x;
            KV[(d4 + 1) * KSTR + row] = v.y;
            KV[(d4 + 2) * KSTR + row] = v.z;
            KV[(d4 + 3) * KSTR + row] = v.w;
        }
        __syncthreads();   // Qs (first iter) + Ks ready

        float s[4][4];
#pragma unroll
        for (int r = 0; r < 4; r++)
#pragma unroll
            for (int c = 0; c < 4; c++) s[r][c] = 0.f;

#pragma unroll 4
        for (int d = 0; d < 128; d++) {
            float q0 = Qs[d * KSTR + ty];
            float q1 = Qs[d * KSTR + ty + 16];
            float q2 = Qs[d * KSTR + ty + 32];
            float q3 = Qs[d * KSTR + ty + 48];
            float k0 = KV[d * KSTR + tx];
            float k1 = KV[d * KSTR + tx + 16];
            float k2 = KV[d * KSTR + tx + 32];
            float k3 = KV[d * KSTR + tx + 48];
            s[0][0] += q0 * k0; s[0][1] += q0 * k1; s[0][2] += q0 * k2; s[0][3] += q0 * k3;
            s[1][0] += q1 * k0; s[1][1] += q1 * k1; s[1][2] += q1 * k2; s[1][3] += q1 * k3;
            s[2][0] += q2 * k0; s[2][1] += q2 * k1; s[2][2] += q2 * k2; s[2][3] += q2 * k3;
            s[3][0] += q3 * k0; s[3][1] += q3 * k1; s[3][2] += q3 * k2; s[3][3] += q3 * k3;
        }
        __syncthreads();   // done reading K; buffer reused for V

        // V tile -> KV as [n][d]
#pragma unroll
        for (int i = 0; i < 8; i++) {
            int lin = tid + 256 * i;
            int row = lin >> 5;
            int d4  = (lin & 31) * 4;
            float4 v = *(const float4*)&g_kv[(xbase + n0 + row) * NKV + HD + d4];
            *(float4*)&KV[row * VSTR + d4] = v;
        }

        const bool diag = (n0 == qm0);
#pragma unroll
        for (int r = 0; r < 4; r++) {
            int qi = ty + 16 * r;   // local row
            if (diag) {
#pragma unroll
                for (int c = 0; c < 4; c++)
                    if (tx + 16 * c > qi) s[r][c] = -1e30f;
            }
            float mx = fmaxf(fmaxf(s[r][0], s[r][1]), fmaxf(s[r][2], s[r][3]));
#pragma unroll
            for (int off = 1; off < 16; off <<= 1)
                mx = fmaxf(mx, __shfl_xor_sync(0xffffffffu, mx, off));
            float mnew  = fmaxf(m_i[r], mx);
            float alpha = __expf(m_i[r] - mnew);
            float rs = 0.f;
#pragma unroll
            for (int c = 0; c < 4; c++) {
                float p = __expf(s[r][c] - mnew);
                s[r][c] = p; rs += p;
            }
#pragma unroll
            for (int off = 1; off < 16; off <<= 1)
                rs += __shfl_xor_sync(0xffffffffu, rs, off);
            m_i[r] = mnew;
            l_i[r] = l_i[r] * alpha + rs;
#pragma unroll
            for (int u = 0; u < 8; u++) acc[r][u] *= alpha;
#pragma unroll
            for (int c = 0; c < 4; c++)
                Ps[qi * PS_STR + tx + 16 * c] = s[r][c];
        }
        __syncthreads();   // V loaded + Ps written

        // PV: acc[r][0..7] += P[row][j] * V[j][tx*8 .. tx*8+7]
#pragma unroll 2
        for (int j = 0; j < BN; j++) {
            float4 v0 = *(const float4*)&KV[j * VSTR + tx * 8];
            float4 v1 = *(const float4*)&KV[j * VSTR + tx * 8 + 4];
#pragma unroll
            for (int r = 0; r < 4; r++) {
                float p = Ps[(ty + 16 * r) * PS_STR + j];
                acc[r][0] += p * v0.x; acc[r][1] += p * v0.y;
                acc[r][2] += p * v0.z; acc[r][3] += p * v0.w;
                acc[r][4] += p * v1.x; acc[r][5] += p * v1.y;
                acc[r][6] += p * v1.z; acc[r][7] += p * v1.w;
            }
        }
        __syncthreads();   // before K overwrites KV next iter
    }

    // Epilogue: out[b, t, h, d] = acc / l
#pragma unroll
    for (int r = 0; r < 4; r++) {
        float inv = 1.0f / l_i[r];
        int t = qm0 + ty + 16 * r;
        float* o = out + (xbase + t) * N_EMBD + h * HD + tx * 8;
        *(float4*)&o[0] = make_float4(acc[r][0] * inv, acc[r][1] * inv,
                                      acc[r][2] * inv, acc[r][3] * inv);
        *(float4*)&o[4] = make_float4(acc[r][4] * inv, acc[r][5] * inv,
                                      acc[r][6] * inv, acc[r][7] * inv);
    }
}

// ---------------------------------------------------------------------------
extern "C" void kernel_launch(void* const* d_in, const int* in_sizes, int n_in,
                              void* d_out, int out_size) {
    const float* x    = (const float*)d_in[0];
    const float* w_kv = (const float*)d_in[1];
    const float* w_q  = (const float*)d_in[2];
    float* out = (float*)d_out;

    // Idempotent; also called on the (non-captured) correctness run first.
    cudaFuncSetAttribute(flash_attn, cudaFuncAttributeMaxDynamicSharedMemorySize, SMEM_BYTES);

    dim3 g1(NTOT / 128, MTOT / 128);   // (18, 32)
    gemm_fused<<<g1, 256>>>(x, w_kv, w_q);

    dim3 g2(TSEQ / BM, BATCH * NHEAD); // (32, 32)
    flash_attn<<<g2, 256, SMEM_BYTES>>>(out);
}

// round 2
// speedup vs baseline: 1.0135x; 1.0135x over previous
#include <cuda_runtime.h>

#define N_EMBD 2048
#define NHEAD  16
#define HD     128
#define BATCH  2
#define TSEQ   2048
#define MTOT   (BATCH * TSEQ)      // 4096
#define KDIM   N_EMBD              // 2048
#define NKV    (2 * HD)            // 256
#define NTOT   (NKV + N_EMBD)      // 2304

// Scratch (allocation-free rule: __device__ globals)
__device__ float g_q [MTOT * N_EMBD];   // 32 MB
__device__ float g_kv[MTOT * NKV];      // 4 MB

// ---------------------------------------------------------------------------
// Fused SGEMM:  C = X[4096,2048] @ W^T, where W = concat(w_kv[256,2048], w_q[2048,2048])
// Tile 128x128x8, 256 threads, 8x8 micro-tile per thread.
// ---------------------------------------------------------------------------
__global__ __launch_bounds__(256, 2)
void gemm_fused(const float* __restrict__ x,
                const float* __restrict__ w_kv,
                const float* __restrict__ w_q) {
    __shared__ float As[8][128];
    __shared__ float Bs[8][128];

    const int n0 = blockIdx.x * 128;
    const int m0 = blockIdx.y * 128;

    const float* Bmat;
    float* C;
    int ldc;
    if (n0 < NKV) { Bmat = w_kv + n0 * KDIM;          C = g_kv + n0;          ldc = NKV;    }
    else          { Bmat = w_q  + (n0 - NKV) * KDIM;  C = g_q  + (n0 - NKV);  ldc = N_EMBD; }

    const int tid  = threadIdx.x;
    const int lrow = tid >> 1;            // 0..127
    const int seg  = (tid & 1) * 4;       // 0 or 4
    const int tx   = tid & 15;
    const int ty   = tid >> 4;

    const float* Ap = x    + (m0 + lrow) * KDIM + seg;
    const float* Bp = Bmat + lrow * KDIM + seg;

    float acc[8][8];
#pragma unroll
    for (int i = 0; i < 8; i++)
#pragma unroll
        for (int j = 0; j < 8; j++) acc[i][j] = 0.f;

    for (int k0 = 0; k0 < KDIM; k0 += 8) {
        float4 av = *(const float4*)(Ap + k0);
        float4 bv = *(const float4*)(Bp + k0);
        As[seg + 0][lrow] = av.x; As[seg + 1][lrow] = av.y;
        As[seg + 2][lrow] = av.z; As[seg + 3][lrow] = av.w;
        Bs[seg + 0][lrow] = bv.x; Bs[seg + 1][lrow] = bv.y;
        Bs[seg + 2][lrow] = bv.z; Bs[seg + 3][lrow] = bv.w;
        __syncthreads();
#pragma unroll
        for (int kk = 0; kk < 8; kk++) {
            float a[8], b[8];
            *(float4*)&a[0] = *(const float4*)&As[kk][ty * 8];
            *(float4*)&a[4] = *(const float4*)&As[kk][ty * 8 + 4];
            *(float4*)&b[0] = *(const float4*)&Bs[kk][tx * 8];
            *(float4*)&b[4] = *(const float4*)&Bs[kk][tx * 8 + 4];
#pragma unroll
            for (int i = 0; i < 8; i++)
#pragma unroll
                for (int j = 0; j < 8; j++)
                    acc[i][j] += a[i] * b[j];
        }
        __syncthreads();
    }

#pragma unroll
    for (int i = 0; i < 8; i++) {
        float* Crow = C + (m0 + ty * 8 + i) * ldc + tx * 8;
        *(float4*)&Crow[0] = make_float4(acc[i][0], acc[i][1], acc[i][2], acc[i][3]);
        *(float4*)&Crow[4] = make_float4(acc[i][4], acc[i][5], acc[i][6], acc[i][7]);
    }
}

// ---------------------------------------------------------------------------
// Flash attention fp32, causal. BM=BN=64, D=128, 256 threads (16x16 grid),
// strided 4x4 score micro-tiles (rows ty+16r, cols tx+16c) for conflict-free
// smem reads. K transposed to [d][n] in smem (stride 65), V kept [n][d]
// (stride 132, float4-aligned). Online softmax via shfl over 16-lane groups.
// ---------------------------------------------------------------------------
#define BM 64
#define BN 64
#define KSTR 65               // [d][n] stride
#define VSTR 132              // [n][d] stride (132*4 = 16B-aligned)
#define QS_SIZE (128 * KSTR)  // 8320 floats
#define KV_SIZE (BN * VSTR)   // 8448 floats (>= 128*KSTR would be 8320; K fits)
#define PS_STR  65
#define SMEM_FLOATS (QS_SIZE + KV_SIZE + BM * PS_STR)
#define SMEM_BYTES  (SMEM_FLOATS * 4)

__global__ __launch_bounds__(256, 1)
void flash_attn(float* __restrict__ out) {
    extern __shared__ float sm[];
    float* Qs = sm;                      // [d][m], stride KSTR
    float* KV = sm + QS_SIZE;            // K: [d][n] stride KSTR  |  V: [n][d] stride VSTR
    float* Ps = sm + QS_SIZE + KV_SIZE;  // [m][n], stride PS_STR

    const int tid = threadIdx.x;
    const int tx  = tid & 15;
    const int ty  = tid >> 4;
    const int mtile = gridDim.x - 1 - blockIdx.x;   // big blocks first
    const int qm0 = mtile * BM;
    const int b   = blockIdx.y >> 4;
    const int h   = blockIdx.y & 15;
    const int xbase = b * TSEQ;
    const float scale = 0.08838834764831845f;       // 1/sqrt(128)

    // Load Q tile (scaled), transpose to [d][m]
#pragma unroll
    for (int i = 0; i < 8; i++) {
        int lin = tid + 256 * i;
        int row = lin >> 5;
        int d4  = (lin & 31) * 4;
        float4 v = *(const float4*)&g_q[(xbase + qm0 + row) * N_EMBD + h * HD + d4];
        Qs[(d4 + 0) * KSTR + row] = v.x * scale;
        Qs[(d4 + 1) * KSTR + row] = v.y * scale;
        Qs[(d4 + 2) * KSTR + row] = v.z * scale;
        Qs[(d4 + 3) * KSTR + row] = v.w * scale;
    }

    float m_i[4], l_i[4], acc[4][8];
#pragma unroll
    for (int r = 0; r < 4; r++) {
        m_i[r] = -1e30f; l_i[r] = 0.f;
#pragma unroll
        for (int u = 0; u < 8; u++) acc[r][u] = 0.f;
    }

    for (int n0 = 0; n0 <= qm0; n0 += BN) {
        // K tile -> KV transposed [d][n]
#pragma unroll
        for (int i = 0; i < 8; i++) {
            int lin = tid + 256 * i;
            int row = lin >> 5;
            int d4  = (lin & 31) * 4;
            float4 v = *(const float4*)&g_kv[(xbase + n0 + row) * NKV + d4];
            KV[(d4 + 0) * KSTR + row] = v.x;
            KV[(d4 + 1) * KSTR + row] = v.y;
            KV[(d4 + 2) * KSTR + row] = v.z;
            KV[(d4 + 3) * KSTR + row] = v.w;
        }
        __syncthreads();   // Qs (first iter) + Ks ready

        float s[4][4];
#pragma unroll
        for (int r = 0; r < 4; r++)
#pragma unroll
            for (int c = 0; c < 4; c++) s[r][c] = 0.f;

#pragma unroll 4
        for (int d = 0; d < 128; d++) {
            float q0 = Qs[d * KSTR + ty];
            float q1 = Qs[d * KSTR + ty + 16];
            float q2 = Qs[d * KSTR + ty + 32];
            float q3 = Qs[d * KSTR + ty + 48];
            float k0 = KV[d * KSTR + tx];
            float k1 = KV[d * KSTR + tx + 16];
            float k2 = KV[d * KSTR + tx + 32];
            float k3 = KV[d * KSTR + tx + 48];
            s[0][0] += q0 * k0; s[0][1] += q0 * k1; s[0][2] += q0 * k2; s[0][3] += q0 * k3;
            s[1][0] += q1 * k0; s[1][1] += q1 * k1; s[1][2] += q1 * k2; s[1][3] += q1 * k3;
            s[2][0] += q2 * k0; s[2][1] += q2 * k1; s[2][2] += q2 * k2; s[2][3] += q2 * k3;
            s[3][0] += q3 * k0; s[3][1] += q3 * k1; s[3][2] += q3 * k2; s[3][3] += q3 * k3;
        }
        __syncthreads();   // done reading K; buffer reused for V

        // V tile -> KV as [n][d]
#pragma unroll
        for (int i = 0; i < 8; i++) {
            int lin = tid + 256 * i;
            int row = lin >> 5;
            int d4  = (lin & 31) * 4;
            float4 v = *(const float4*)&g_kv[(xbase + n0 + row) * NKV + HD + d4];
            *(float4*)&KV[row * VSTR + d4] = v;
        }

        const bool diag = (n0 == qm0);
#pragma unroll
        for (int r = 0; r < 4; r++) {
            int qi = ty + 16 * r;   // local row
            if (diag) {
#pragma unroll
                for (int c = 0; c < 4; c++)
                    if (tx + 16 * c > qi) s[r][c] = -1e30f;
            }
            float mx = fmaxf(fmaxf(s[r][0], s[r][1]), fmaxf(s[r][2], s[r][3]));
#pragma unroll
            for (int off = 1; off < 16; off <<= 1)
                mx = fmaxf(mx, __shfl_xor_sync(0xffffffffu, mx, off));
            float mnew  = fmaxf(m_i[r], mx);
            float alpha = __expf(m_i[r] - mnew);
            float rs = 0.f;
#pragma unroll
            for (int c = 0; c < 4; c++) {
                float p = __expf(s[r][c] - mnew);
                s[r][c] = p; rs += p;
            }
#pragma unroll
            for (int off = 1; off < 16; off <<= 1)
                rs += __shfl_xor_sync(0xffffffffu, rs, off);
            m_i[r] = mnew;
            l_i[r] = l_i[r] * alpha + rs;
#pragma unroll
            for (int u = 0; u < 8; u++) acc[r][u] *= alpha;
#pragma unroll
            for (int c = 0; c < 4; c++)
                Ps[qi * PS_STR + tx + 16 * c] = s[r][c];
        }
        __syncthreads();   // V loaded + Ps written

        // PV: acc[r][0..7] += P[row][j] * V[j][tx*8 .. tx*8+7]
#pragma unroll 2
        for (int j = 0; j < BN; j++) {
            float4 v0 = *(const float4*)&KV[j * VSTR + tx * 8];
            float4 v1 = *(const float4*)&KV[j * VSTR + tx * 8 + 4];
#pragma unroll
            for (int r = 0; r < 4; r++) {
                float p = Ps[(ty + 16 * r) * PS_STR + j];
                acc[r][0] += p * v0.x; acc[r][1] += p * v0.y;
                acc[r][2] += p * v0.z; acc[r][3] += p * v0.w;
                acc[r][4] += p * v1.x; acc[r][5] += p * v1.y;
                acc[r][6] += p * v1.z; acc[r][7] += p * v1.w;
            }
        }
        __syncthreads();   // before K overwrites KV next iter
    }

    // Epilogue: out[b, t, h, d] = acc / l
#pragma unroll
    for (int r = 0; r < 4; r++) {
        float inv = 1.0f / l_i[r];
        int t = qm0 + ty + 16 * r;
        float* o = out + (xbase + t) * N_EMBD + h * HD + tx * 8;
        *(float4*)&o[0] = make_float4(acc[r][0] * inv, acc[r][1] * inv,
                                      acc[r][2] * inv, acc[r][3] * inv);
        *(float4*)&o[4] = make_float4(acc[r][4] * inv, acc[r][5] * inv,
                                      acc[r][6] * inv, acc[r][7] * inv);
    }
}

// ---------------------------------------------------------------------------
extern "C" void kernel_launch(void* const* d_in, const int* in_sizes, int n_in,
                              void* d_out, int out_size) {
    const float* x    = (const float*)d_in[0];
    const float* w_kv = (const float*)d_in[1];
    const float* w_q  = (const float*)d_in[2];
    float* out = (float*)d_out;

    // Idempotent; also called on the (non-captured) correctness run first.
    cudaFuncSetAttribute(flash_attn, cudaFuncAttributeMaxDynamicSharedMemorySize, SMEM_BYTES);

    dim3 g1(NTOT / 128, MTOT / 128);   // (18, 32)
    gemm_fused<<<g1, 256>>>(x, w_kv, w_q);

    dim3 g2(TSEQ / BM, BATCH * NHEAD); // (32, 32)
    flash_attn<<<g2, 256, SMEM_BYTES>>>(out);
}

// round 4
// speedup vs baseline: 6.6942x; 6.6047x over previous
#include <cuda_runtime.h>
#include <cuda_fp16.h>
#include <cstdint>

#define N_EMBD 2048
#define NHEAD  16
#define HD     128
#define BATCH  2
#define TSEQ   2048
#define MTOT   (BATCH * TSEQ)
#define KDIM   N_EMBD
#define NTOT   2304
#define QSCALE 0.08838834764831845f

__device__ __half g_xh[MTOT * KDIM];
__device__ __half g_wh[NTOT * KDIM];
__device__ __half g_qh[MTOT * N_EMBD];
__device__ __half g_kh[MTOT * HD];
__device__ __half g_vt[BATCH * HD * TSEQ];

// ---------------- helpers ----------------
__device__ __forceinline__ uint32_t smem_u32(const void* p) {
    uint32_t a;
    asm("{ .reg .u64 t; cvta.to.shared.u64 t, %1; cvt.u32.u64 %0, t; }" : "=r"(a) : "l"(p));
    return a;
}
#define CP16(sm, gm)  asm volatile("cp.async.cg.shared.global [%0], [%1], 16;" :: "r"(sm), "l"(gm))
#define CP_COMMIT()   asm volatile("cp.async.commit_group;" ::: "memory")
#define CP_WAIT0()    asm volatile("cp.async.wait_group 0;" ::: "memory")
#define CP_WAIT1()    asm volatile("cp.async.wait_group 1;" ::: "memory")

#define LDSM4(r0, r1, r2, r3, a) \
    asm volatile("ldmatrix.sync.aligned.m8n8.x4.shared.b16 {%0,%1,%2,%3}, [%4];" \
                 : "=r"(r0), "=r"(r1), "=r"(r2), "=r"(r3) : "r"(a))
#define LDSM2(r0, r1, a) \
    asm volatile("ldmatrix.sync.aligned.m8n8.x2.shared.b16 {%0,%1}, [%2];" \
                 : "=r"(r0), "=r"(r1) : "r"(a))
#define MMA16816(c, a, b) \
    asm volatile("mma.sync.aligned.m16n8k16.row.col.f32.f16.f16.f32 " \
                 "{%0,%1,%2,%3}, {%4,%5,%6,%7}, {%8,%9}, {%0,%1,%2,%3};" \
                 : "+f"((c)[0]), "+f"((c)[1]), "+f"((c)[2]), "+f"((c)[3]) \
                 : "r"((a)[0]), "r"((a)[1]), "r"((a)[2]), "r"((a)[3]), "r"((b)[0]), "r"((b)[1]))

__device__ __forceinline__ uint32_t h2pack(float a, float b) {
    __half2 h = __floats2half2_rn(a, b);
    return *(uint32_t*)&h;
}

// ---------------- kernel 0: fp32 -> fp16 ----------------
__global__ void convert_inputs(const float* __restrict__ x,
                               const float* __restrict__ wkv,
                               const float* __restrict__ wq) {
    const int stride = gridDim.x * blockDim.x;
    const int t0 = blockIdx.x * blockDim.x + threadIdx.x;
    for (int i = t0; i < MTOT * KDIM / 4; i += stride) {
        float4 v = ((const float4*)x)[i];
        *(uint2*)&g_xh[4 * i] = make_uint2(h2pack(v.x, v.y), h2pack(v.z, v.w));
    }
    for (int i = t0; i < 256 * KDIM / 4; i += stride) {
        float4 v = ((const float4*)wkv)[i];
        *(uint2*)&g_wh[4 * i] = make_uint2(h2pack(v.x, v.y), h2pack(v.z, v.w));
    }
    for (int i = t0; i < N_EMBD * KDIM / 4; i += stride) {
        float4 v = ((const float4*)wq)[i];
        *(uint2*)&g_wh[256 * KDIM + 4 * i] = make_uint2(h2pack(v.x, v.y), h2pack(v.z, v.w));
    }
}

// ---------------- kernel 1: projection GEMM (mma.sync) ----------------
#define ASTR 40                      // halves per smem row (80B, conflict-free)
#define ATILE (128 * ASTR)           // halves per buffer
#define GEMM_SMEM (4 * ATILE * 2)    // A(2buf) + B(2buf) bytes

__global__ __launch_bounds__(256, 1)
void gemm_tc() {
    extern __shared__ __half sm[];
    __half* As = sm;                 // [2][128][ASTR]
    __half* Bs = sm + 2 * ATILE;
    const uint32_t sbA = smem_u32(As), sbB = smem_u32(Bs);

    const int tid = threadIdx.x, wid = tid >> 5, lane = tid & 31;
    const int n0 = blockIdx.x * 128, m0 = blockIdx.y * 128;
    const int wm = (wid & 1) * 64, wn = (wid >> 1) * 32;

    const __half* Ag = g_xh + (size_t)m0 * KDIM;
    const __half* Bg = g_wh + (size_t)n0 * KDIM;

    const int lr = tid >> 1;              // row 0..127
    const int lc0 = (tid & 1) * 2;        // chunk base (of 4 16B-chunks per row)

    // pipeline issue for k-chunk g into buffer (g&1)
    auto issue = [&](int g) {
        const uint32_t bo = (uint32_t)(g & 1) * ATILE * 2;
#pragma unroll
        for (int i = 0; i < 2; i++) {
            int c = lc0 + i;
            CP16(sbA + bo + (lr * ASTR + c * 8) * 2, Ag + (size_t)lr * KDIM + g * 32 + c * 8);
            CP16(sbB + bo + (lr * ASTR + c * 8) * 2, Bg + (size_t)lr * KDIM + g * 32 + c * 8);
        }
        CP_COMMIT();
    };

    float acc[4][4][4];
#pragma unroll
    for (int mt = 0; mt < 4; mt++)
#pragma unroll
        for (int nt = 0; nt < 4; nt++)
#pragma unroll
            for (int e = 0; e < 4; e++) acc[mt][nt][e] = 0.f;

    issue(0);
    issue(1);

    const int NIT = KDIM / 32;            // 64
    for (int j = 0; j < NIT; j++) {
        if (j + 1 < NIT) CP_WAIT1(); else CP_WAIT0();
        __syncthreads();
        const uint32_t bo = (uint32_t)(j & 1) * ATILE * 2;
#pragma unroll
        for (int ks = 0; ks < 2; ks++) {
            uint32_t af[4][4];
#pragma unroll
            for (int mt = 0; mt < 4; mt++) {
                uint32_t a = sbA + bo +
                    ((wm + mt * 16 + (lane & 15)) * ASTR + ks * 16 + (lane >> 4) * 8) * 2;
                LDSM4(af[mt][0], af[mt][1], af[mt][2], af[mt][3], a);
            }
#pragma unroll
            for (int nt = 0; nt < 4; nt++) {
                uint32_t bf[2];
                uint32_t a = sbB + bo +
                    ((wn + nt * 8 + (lane & 7)) * ASTR + ks * 16 + ((lane >> 3) & 1) * 8) * 2;
                LDSM2(bf[0], bf[1], a);
#pragma unroll
                for (int mt = 0; mt < 4; mt++) MMA16816(acc[mt][nt], af[mt], bf);
            }
        }
        __syncthreads();
        if (j + 2 < NIT) issue(j + 2);
    }

    // epilogue: bx==0 -> K, bx==1 -> V(transposed), else Q (scaled)
    const int role = (blockIdx.x == 0) ? 0 : (blockIdx.x == 1) ? 1 : 2;
    const int r0 = lane >> 2, c0 = (lane & 3) * 2;
#pragma unroll
    for (int mt = 0; mt < 4; mt++) {
#pragma unroll
        for (int nt = 0; nt < 4; nt++) {
            int tokA = m0 + wm + mt * 16 + r0;
            int col = wn + nt * 8 + c0;
            float* c = acc[mt][nt];
            if (role == 0) {
                *(uint32_t*)&g_kh[(size_t)tokA * HD + col] = h2pack(c[0], c[1]);
                *(uint32_t*)&g_kh[(size_t)(tokA + 8) * HD + col] = h2pack(c[2], c[3]);
            } else if (role == 2) {
                size_t base = (size_t)tokA * N_EMBD + (n0 - 256) + col;
                *(uint32_t*)&g_qh[base] = h2pack(c[0] * QSCALE, c[1] * QSCALE);
                *(uint32_t*)&g_qh[base + 8 * N_EMBD] = h2pack(c[2] * QSCALE, c[3] * QSCALE);
            } else {
                int bA = tokA >> 11, tl = tokA & 2047;
                int bB = (tokA + 8) >> 11, tl2 = (tokA + 8) & 2047;
                g_vt[(size_t)(bA * HD + col) * TSEQ + tl] = __float2half_rn(c[0]);
                g_vt[(size_t)(bA * HD + col + 1) * TSEQ + tl] = __float2half_rn(c[1]);
                g_vt[(size_t)(bB * HD + col) * TSEQ + tl2] = __float2half_rn(c[2]);
                g_vt[(size_t)(bB * HD + col + 1) * TSEQ + tl2] = __float2half_rn(c[3]);
            }
        }
    }
}

// ---------------- kernel 2: flash attention (mma.sync, FA2-style) ----------------
#define QSTR 136                       // halves (272B rows)
#define KSTR2 136
#define VSTR2 72
#define QOFF  (128 * QSTR)             // halves
#define KBUF  (64 * KSTR2)
#define VOFF  (QOFF + 2 * KBUF)
#define VBUF  (128 * VSTR2)
#define ATT_SMEM ((VOFF + 2 * VBUF) * 2)

__global__ __launch_bounds__(256, 1)
void attn_tc(float* __restrict__ out) {
    extern __shared__ __half sm[];
    const uint32_t sb = smem_u32(sm);
    const uint32_t sbK = sb + QOFF * 2, sbV = sb + VOFF * 2;

    const int tid = threadIdx.x, wid = tid >> 5, lane = tid & 31;
    const int qt = (int)gridDim.x - 1 - (int)blockIdx.x;     // big tiles first
    const int qm0 = qt * 128;
    const int b = blockIdx.y >> 4, h = blockIdx.y & 15;

    const __half* Qg = g_qh + (size_t)(b * TSEQ + qm0) * N_EMBD + h * HD;
    const __half* Kg = g_kh + (size_t)b * TSEQ * HD;
    const __half* Vg = g_vt + (size_t)b * HD * TSEQ;

    // load Q tile [128][128] into smem
#pragma unroll
    for (int i = 0; i < 8; i++) {
        int id = tid + 256 * i, r = id >> 4, c = id & 15;
        *(uint4*)&sm[r * QSTR + c * 8] = *(const uint4*)(Qg + (size_t)r * N_EMBD + c * 8);
    }

    auto issue = [&](int j, int buf) {
#pragma unroll
        for (int i = 0; i < 4; i++) {                      // K chunk [64][128]
            int id = tid + 256 * i, r = id >> 4, c = id & 15;
            CP16(sbK + (buf * KBUF + r * KSTR2 + c * 8) * 2,
                 Kg + (size_t)(j * 64 + r) * HD + c * 8);
        }
#pragma unroll
        for (int i = 0; i < 4; i++) {                      // V^T chunk [128][64]
            int id = tid + 256 * i, r = id >> 3, c = id & 7;
            CP16(sbV + (buf * VBUF + r * VSTR2 + c * 8) * 2,
                 Vg + (size_t)r * TSEQ + j * 64 + c * 8);
        }
        CP_COMMIT();
    };

    const int nch = 2 * qt + 2;
    issue(0, 0);
    if (nch > 1) issue(1, 1);
    __syncthreads();                                       // Q tile visible

    // Q fragments register-resident
    uint32_t qa[8][4];
#pragma unroll
    for (int kt = 0; kt < 8; kt++) {
        uint32_t a = sb + ((wid * 16 + (lane & 15)) * QSTR + kt * 16 + (lane >> 4) * 8) * 2;
        LDSM4(qa[kt][0], qa[kt][1], qa[kt][2], qa[kt][3], a);
    }

    float o[16][4];
#pragma unroll
    for (int nt = 0; nt < 16; nt++)
#pragma unroll
        for (int e = 0; e < 4; e++) o[nt][e] = 0.f;
    float m_lo = -1e30f, m_hi = -1e30f, l_lo = 0.f, l_hi = 0.f;

    const int rl = lane >> 2;                              // 0..7
    const int rowl = wid * 16 + rl;                        // local row (and +8)

    for (int j = 0; j < nch; j++) {
        if (j + 1 < nch) CP_WAIT1(); else CP_WAIT0();
        __syncthreads();
        const int buf = j & 1;

        // S = Q @ K^T for this 64-key chunk
        float s[8][4];
#pragma unroll
        for (int nt = 0; nt < 8; nt++) {
            s[nt][0] = s[nt][1] = s[nt][2] = s[nt][3] = 0.f;
            uint32_t abase = sbK + (buf * KBUF + (nt * 8 + (lane & 7)) * KSTR2 +
                                    ((lane >> 3) & 1) * 8) * 2;
#pragma unroll
            for (int kt = 0; kt < 8; kt++) {
                uint32_t bf[2];
                LDSM2(bf[0], bf[1], abase + kt * 32);
                MMA16816(s[nt], qa[kt], bf);
            }
        }

        // causal mask (only last two chunks of this block)
        if (j >= 2 * qt) {
            const int rel = j * 64 - qm0 + qt * 128 - qt * 128;  // = j*64 - 0 rel to block
            const int shift = j * 64 - 2 * qt * 64;              // 0 or 64
#pragma unroll
            for (int nt = 0; nt < 8; nt++) {
                int cl = shift + nt * 8 + (lane & 3) * 2;
                if (cl > rowl)     s[nt][0] = -1e30f;
                if (cl + 1 > rowl) s[nt][1] = -1e30f;
                if (cl > rowl + 8)     s[nt][2] = -1e30f;
                if (cl + 1 > rowl + 8) s[nt][3] = -1e30f;
            }
            (void)rel;
        }

        // online softmax
        float mx_lo = -1e30f, mx_hi = -1e30f;
#pragma unroll
        for (int nt = 0; nt < 8; nt++) {
            mx_lo = fmaxf(mx_lo, fmaxf(s[nt][0], s[nt][1]));
            mx_hi = fmaxf(mx_hi, fmaxf(s[nt][2], s[nt][3]));
        }
        mx_lo = fmaxf(mx_lo, __shfl_xor_sync(0xffffffffu, mx_lo, 1));
        mx_lo = fmaxf(mx_lo, __shfl_xor_sync(0xffffffffu, mx_lo, 2));
        mx_hi = fmaxf(mx_hi, __shfl_xor_sync(0xffffffffu, mx_hi, 1));
        mx_hi = fmaxf(mx_hi, __shfl_xor_sync(0xffffffffu, mx_hi, 2));

        float mn_lo = fmaxf(m_lo, mx_lo), mn_hi = fmaxf(m_hi, mx_hi);
        float al_lo = __expf(m_lo - mn_lo), al_hi = __expf(m_hi - mn_hi);
        m_lo = mn_lo; m_hi = mn_hi;

        float sa_lo = 0.f, sa_hi = 0.f;
#pragma unroll
        for (int nt = 0; nt < 8; nt++) {
            s[nt][0] = __expf(s[nt][0] - mn_lo);
            s[nt][1] = __expf(s[nt][1] - mn_lo);
            s[nt][2] = __expf(s[nt][2] - mn_hi);
            s[nt][3] = __expf(s[nt][3] - mn_hi);
            sa_lo += s[nt][0] + s[nt][1];
            sa_hi += s[nt][2] + s[nt][3];
        }
        sa_lo += __shfl_xor_sync(0xffffffffu, sa_lo, 1);
        sa_lo += __shfl_xor_sync(0xffffffffu, sa_lo, 2);
        sa_hi += __shfl_xor_sync(0xffffffffu, sa_hi, 1);
        sa_hi += __shfl_xor_sync(0xffffffffu, sa_hi, 2);
        l_lo = l_lo * al_lo + sa_lo;
        l_hi = l_hi * al_hi + sa_hi;

        // rescale O, pack P to fp16 A-fragments
#pragma unroll
        for (int nt = 0; nt < 16; nt++) {
            o[nt][0] *= al_lo; o[nt][1] *= al_lo;
            o[nt][2] *= al_hi; o[nt][3] *= al_hi;
        }
        uint32_t pa[4][4];
#pragma unroll
        for (int kt = 0; kt < 4; kt++) {
            pa[kt][0] = h2pack(s[2 * kt][0], s[2 * kt][1]);
            pa[kt][1] = h2pack(s[2 * kt][2], s[2 * kt][3]);
            pa[kt][2] = h2pack(s[2 * kt + 1][0], s[2 * kt + 1][1]);
            pa[kt][3] = h2pack(s[2 * kt + 1][2], s[2 * kt + 1][3]);
        }

        // O += P @ V
#pragma unroll
        for (int nt = 0; nt < 16; nt++) {
            uint32_t abase = sbV + (buf * VBUF + (nt * 8 + (lane & 7)) * VSTR2 +
                                    ((lane >> 3) & 1) * 8) * 2;
#pragma unroll
            for (int kt = 0; kt < 4; kt++) {
                uint32_t bf[2];
                LDSM2(bf[0], bf[1], abase + kt * 32);
                MMA16816(o[nt], pa[kt], bf);
            }
        }
        __syncthreads();
        if (j + 2 < nch) issue(j + 2, buf);
    }

    // epilogue
    const float inv_lo = 1.0f / l_lo, inv_hi = 1.0f / l_hi;
    const size_t rA = (size_t)(b * TSEQ + qm0 + rowl) * N_EMBD + h * HD + (lane & 3) * 2;
    const size_t rB = rA + 8 * N_EMBD;
#pragma unroll
    for (int nt = 0; nt < 16; nt++) {
        *(float2*)&out[rA + nt * 8] = make_float2(o[nt][0] * inv_lo, o[nt][1] * inv_lo);
        *(float2*)&out[rB + nt * 8] = make_float2(o[nt][2] * inv_hi, o[nt][3] * inv_hi);
    }
}

// ---------------------------------------------------------------------------
extern "C" void kernel_launch(void* const* d_in, const int* in_sizes, int n_in,
                              void* d_out, int out_size) {
    const float* x    = (const float*)d_in[0];
    const float* w_kv = (const float*)d_in[1];
    const float* w_q  = (const float*)d_in[2];
    float* out = (float*)d_out;

    cudaFuncSetAttribute(gemm_tc, cudaFuncAttributeMaxDynamicSharedMemorySize, GEMM_SMEM);
    cudaFuncSetAttribute(attn_tc, cudaFuncAttributeMaxDynamicSharedMemorySize, ATT_SMEM);

    convert_inputs<<<512, 256>>>(x, w_kv, w_q);
    dim3 g1(NTOT / 128, MTOT / 128);        // (18, 32)
    gemm_tc<<<g1, 256, GEMM_SMEM>>>();
    dim3 g2(TSEQ / 128, BATCH * NHEAD);     // (16, 32)
    attn_tc<<<g2, 256, ATT_SMEM>>>(out);
}

// round 6
// speedup vs baseline: 7.7157x; 1.1526x over previous
#include <cuda_runtime.h>
#include <cuda_fp16.h>
#include <cstdint>

#define N_EMBD 2048
#define NHEAD  16
#define HD     128
#define BATCH  2
#define TSEQ   2048
#define MTOT   (BATCH * TSEQ)
#define KDIM   N_EMBD
#define NTOT   2304
#define QSCALE 0.08838834764831845f

__device__ __half g_xh[MTOT * KDIM];
__device__ __half g_wh[NTOT * KDIM];
__device__ __half g_qh[MTOT * N_EMBD];
__device__ __half g_kh[MTOT * HD];
__device__ __half g_vt[BATCH * HD * TSEQ];

// ---------------- helpers ----------------
__device__ __forceinline__ uint32_t smem_u32(const void* p) {
    uint32_t a;
    asm("{ .reg .u64 t; cvta.to.shared.u64 t, %1; cvt.u32.u64 %0, t; }" : "=r"(a) : "l"(p));
    return a;
}
#define CP16(sm, gm)  asm volatile("cp.async.cg.shared.global [%0], [%1], 16;" :: "r"(sm), "l"(gm))
#define CP_COMMIT()   asm volatile("cp.async.commit_group;" ::: "memory")
#define CP_WAIT0()    asm volatile("cp.async.wait_group 0;" ::: "memory")
#define CP_WAIT1()    asm volatile("cp.async.wait_group 1;" ::: "memory")

#define LDSM4(r0, r1, r2, r3, a) \
    asm volatile("ldmatrix.sync.aligned.m8n8.x4.shared.b16 {%0,%1,%2,%3}, [%4];" \
                 : "=r"(r0), "=r"(r1), "=r"(r2), "=r"(r3) : "r"(a))
#define MMA16816(c, a, b0, b1) \
    asm volatile("mma.sync.aligned.m16n8k16.row.col.f32.f16.f16.f32 " \
                 "{%0,%1,%2,%3}, {%4,%5,%6,%7}, {%8,%9}, {%0,%1,%2,%3};" \
                 : "+f"((c)[0]), "+f"((c)[1]), "+f"((c)[2]), "+f"((c)[3]) \
                 : "r"((a)[0]), "r"((a)[1]), "r"((a)[2]), "r"((a)[3]), "r"(b0), "r"(b1))

__device__ __forceinline__ uint32_t h2pack(float a, float b) {
    __half2 h = __floats2half2_rn(a, b);
    return *(uint32_t*)&h;
}
// B-operand ldmatrix x4: covers n16 x k16 (two n8k16 fragments).
__device__ __forceinline__ uint32_t bfrag_addr(uint32_t base, int lane, int nbase,
                                               int kcol, int STR) {
    int row = nbase + ((lane >> 4) << 3) + (lane & 7);
    int col = kcol + ((lane >> 3) & 1) * 8;
    return base + (uint32_t)(row * STR + col) * 2u;
}

// ---------------- kernel 0: fp32 -> fp16 ----------------
__global__ void convert_inputs(const float* __restrict__ x,
                               const float* __restrict__ wkv,
                               const float* __restrict__ wq) {
    const int stride = gridDim.x * blockDim.x;
    const int t0 = blockIdx.x * blockDim.x + threadIdx.x;
    for (int i = t0; i < MTOT * KDIM / 4; i += stride) {
        float4 v = ((const float4*)x)[i];
        *(uint2*)&g_xh[4 * i] = make_uint2(h2pack(v.x, v.y), h2pack(v.z, v.w));
    }
    for (int i = t0; i < 256 * KDIM / 4; i += stride) {
        float4 v = ((const float4*)wkv)[i];
        *(uint2*)&g_wh[4 * i] = make_uint2(h2pack(v.x, v.y), h2pack(v.z, v.w));
    }
    for (int i = t0; i < N_EMBD * KDIM / 4; i += stride) {
        float4 v = ((const float4*)wq)[i];
        *(uint2*)&g_wh[256 * KDIM + 4 * i] = make_uint2(h2pack(v.x, v.y), h2pack(v.z, v.w));
    }
}

// ---------------- kernel 1: projection GEMM, 256x128x32, mma.sync ----------------
#define ASTR 40                          // halves per smem row (80B)
#define ATILE (256 * ASTR)
#define BTILE (128 * ASTR)
#define GEMM_SMEM ((2 * ATILE + 2 * BTILE) * 2)

__global__ __launch_bounds__(256, 1)
void gemm_tc() {
    extern __shared__ __half sm[];
    const uint32_t sbA = smem_u32(sm);
    const uint32_t sbB = sbA + 2 * ATILE * 2;

    const int tid = threadIdx.x, wid = tid >> 5, lane = tid & 31;
    const int n0 = blockIdx.x * 128, m0 = blockIdx.y * 256;
    const int wm = (wid & 3) * 64, wn = (wid >> 2) * 64;

    const __half* Ag = g_xh + (size_t)m0 * KDIM;
    const __half* Bg = g_wh + (size_t)n0 * KDIM;

    auto issue = [&](int g) {
        const uint32_t boA = (uint32_t)(g & 1) * ATILE * 2;
        const uint32_t boB = (uint32_t)(g & 1) * BTILE * 2;
#pragma unroll
        for (int i = 0; i < 4; i++) {                     // A: 256 rows x 4 chunks
            int idx = tid + 256 * i, r = idx >> 2, c = idx & 3;
            CP16(sbA + boA + (uint32_t)(r * ASTR + c * 8) * 2,
                 Ag + (size_t)r * KDIM + g * 32 + c * 8);
        }
#pragma unroll
        for (int i = 0; i < 2; i++) {                     // B: 128 rows x 4 chunks
            int idx = tid + 256 * i, r = idx >> 2, c = idx & 3;
            CP16(sbB + boB + (uint32_t)(r * ASTR + c * 8) * 2,
                 Bg + (size_t)r * KDIM + g * 32 + c * 8);
        }
        CP_COMMIT();
    };

    float acc[4][8][4];
#pragma unroll
    for (int mt = 0; mt < 4; mt++)
#pragma unroll
        for (int nt = 0; nt < 8; nt++)
#pragma unroll
            for (int e = 0; e < 4; e++) acc[mt][nt][e] = 0.f;

    issue(0);
    issue(1);

    const int NIT = KDIM / 32;                            // 64
    for (int j = 0; j < NIT; j++) {
        if (j + 1 < NIT) CP_WAIT1(); else CP_WAIT0();
        __syncthreads();
        const uint32_t boA = (uint32_t)(j & 1) * ATILE * 2;
        const uint32_t boB = (uint32_t)(j & 1) * BTILE * 2;
#pragma unroll
        for (int ks = 0; ks < 2; ks++) {
            uint32_t af[4][4];
#pragma unroll
            for (int mt = 0; mt < 4; mt++) {
                uint32_t a = sbA + boA +
                    (uint32_t)((wm + mt * 16 + (lane & 15)) * ASTR + ks * 16 + (lane >> 4) * 8) * 2;
                LDSM4(af[mt][0], af[mt][1], af[mt][2], af[mt][3], a);
            }
#pragma unroll
            for (int ntp = 0; ntp < 4; ntp++) {
                uint32_t b0, b1, b2, b3;
                LDSM4(b0, b1, b2, b3,
                      bfrag_addr(sbB + boB, lane, wn + ntp * 16, ks * 16, ASTR));
#pragma unroll
                for (int mt = 0; mt < 4; mt++) {
                    MMA16816(acc[mt][2 * ntp],     af[mt], b0, b1);
                    MMA16816(acc[mt][2 * ntp + 1], af[mt], b2, b3);
                }
            }
        }
        __syncthreads();
        if (j + 2 < NIT) issue(j + 2);
    }

    // epilogue: bx==0 -> K, bx==1 -> V(transposed), else Q (scaled)
    const int role = (blockIdx.x == 0) ? 0 : (blockIdx.x == 1) ? 1 : 2;
    const int r0 = lane >> 2, c0 = (lane & 3) * 2;
#pragma unroll
    for (int mt = 0; mt < 4; mt++) {
#pragma unroll
        for (int nt = 0; nt < 8; nt++) {
            int tokA = m0 + wm + mt * 16 + r0;
            int col = wn + nt * 8 + c0;
            float* c = acc[mt][nt];
            if (role == 0) {
                *(uint32_t*)&g_kh[(size_t)tokA * HD + col] = h2pack(c[0], c[1]);
                *(uint32_t*)&g_kh[(size_t)(tokA + 8) * HD + col] = h2pack(c[2], c[3]);
            } else if (role == 2) {
                size_t base = (size_t)tokA * N_EMBD + (n0 - 256) + col;
                *(uint32_t*)&g_qh[base] = h2pack(c[0] * QSCALE, c[1] * QSCALE);
                *(uint32_t*)&g_qh[base + 8 * N_EMBD] = h2pack(c[2] * QSCALE, c[3] * QSCALE);
            } else {
                int bA = tokA >> 11, tl = tokA & 2047;
                int bB = (tokA + 8) >> 11, tl2 = (tokA + 8) & 2047;
                g_vt[(size_t)(bA * HD + col) * TSEQ + tl] = __float2half_rn(c[0]);
                g_vt[(size_t)(bA * HD + col + 1) * TSEQ + tl] = __float2half_rn(c[1]);
                g_vt[(size_t)(bB * HD + col) * TSEQ + tl2] = __float2half_rn(c[2]);
                g_vt[(size_t)(bB * HD + col + 1) * TSEQ + tl2] = __float2half_rn(c[3]);
            }
        }
    }
}

// ---------------- kernel 2: flash attention, BM=128, BN=128 ----------------
#define QSTR 136                          // halves per row
#define TBUF (128 * QSTR)                 // one 128x128 tile (halves)
#define KOFF (TBUF)
#define VOFF (3 * TBUF)
#define ATT_SMEM (5 * TBUF * 2)           // Q + 2K + 2V = 174,080 B

__global__ __launch_bounds__(256, 1)
void attn_tc(float* __restrict__ out) {
    extern __shared__ __half sm[];
    const uint32_t sb = smem_u32(sm);
    const uint32_t sbK = sb + KOFF * 2, sbV = sb + VOFF * 2;

    const int tid = threadIdx.x, wid = tid >> 5, lane = tid & 31;
    const int qt = (int)gridDim.x - 1 - (int)blockIdx.x;   // big tiles first
    const int qm0 = qt * 128;
    const int b = blockIdx.y >> 4, h = blockIdx.y & 15;

    const __half* Qg = g_qh + (size_t)(b * TSEQ + qm0) * N_EMBD + h * HD;
    const __half* Kg = g_kh + (size_t)b * TSEQ * HD;
    const __half* Vg = g_vt + (size_t)b * HD * TSEQ;

    // load Q tile [128][128]
#pragma unroll
    for (int i = 0; i < 8; i++) {
        int id = tid + 256 * i, r = id >> 4, c = id & 15;
        *(uint4*)&sm[r * QSTR + c * 8] = *(const uint4*)(Qg + (size_t)r * N_EMBD + c * 8);
    }

    auto issue = [&](int j, int buf) {
#pragma unroll
        for (int i = 0; i < 8; i++) {                      // K chunk [128 keys][128 d]
            int id = tid + 256 * i, r = id >> 4, c = id & 15;
            CP16(sbK + (uint32_t)(buf * TBUF + r * QSTR + c * 8) * 2,
                 Kg + (size_t)(j * 128 + r) * HD + c * 8);
        }
#pragma unroll
        for (int i = 0; i < 8; i++) {                      // V^T chunk [128 d][128 keys]
            int id = tid + 256 * i, r = id >> 4, c = id & 15;
            CP16(sbV + (uint32_t)(buf * TBUF + r * QSTR + c * 8) * 2,
                 Vg + (size_t)r * TSEQ + j * 128 + c * 8);
        }
        CP_COMMIT();
    };

    const int nch = qt + 1;
    issue(0, 0);
    if (nch > 1) issue(1, 1);
    __syncthreads();

    // Q fragments register-resident
    uint32_t qa[8][4];
#pragma unroll
    for (int kt = 0; kt < 8; kt++) {
        uint32_t a = sb + (uint32_t)((wid * 16 + (lane & 15)) * QSTR + kt * 16 + (lane >> 4) * 8) * 2;
        LDSM4(qa[kt][0], qa[kt][1], qa[kt][2], qa[kt][3], a);
    }

    float o[16][4];
#pragma unroll
    for (int nt = 0; nt < 16; nt++)
#pragma unroll
        for (int e = 0; e < 4; e++) o[nt][e] = 0.f;
    float m_lo = -1e30f, m_hi = -1e30f, l_lo = 0.f, l_hi = 0.f;

    const int rowl = wid * 16 + (lane >> 2);               // local row (and +8)

    for (int j = 0; j < nch; j++) {
        if (j + 1 < nch) CP_WAIT1(); else CP_WAIT0();
        __syncthreads();
        const int buf = j & 1;
        const uint32_t kb = sbK + (uint32_t)(buf * TBUF) * 2;
        const uint32_t vb = sbV + (uint32_t)(buf * TBUF) * 2;

        // S = Q @ K^T  (128 keys)
        float s[16][4];
#pragma unroll
        for (int ntp = 0; ntp < 8; ntp++) {
            s[2 * ntp][0] = s[2 * ntp][1] = s[2 * ntp][2] = s[2 * ntp][3] = 0.f;
            s[2 * ntp + 1][0] = s[2 * ntp + 1][1] = s[2 * ntp + 1][2] = s[2 * ntp + 1][3] = 0.f;
#pragma unroll
            for (int kt = 0; kt < 8; kt++) {
                uint32_t b0, b1, b2, b3;
                LDSM4(b0, b1, b2, b3, bfrag_addr(kb, lane, ntp * 16, kt * 16, QSTR));
                MMA16816(s[2 * ntp],     qa[kt], b0, b1);
                MMA16816(s[2 * ntp + 1], qa[kt], b2, b3);
            }
        }

        // causal mask (diagonal chunk only)
        if (j == qt) {
#pragma unroll
            for (int nt = 0; nt < 16; nt++) {
                int cl = nt * 8 + (lane & 3) * 2;
                if (cl > rowl)         s[nt][0] = -1e30f;
                if (cl + 1 > rowl)     s[nt][1] = -1e30f;
                if (cl > rowl + 8)     s[nt][2] = -1e30f;
                if (cl + 1 > rowl + 8) s[nt][3] = -1e30f;
            }
        }

        // online softmax
        float mx_lo = -1e30f, mx_hi = -1e30f;
#pragma unroll
        for (int nt = 0; nt < 16; nt++) {
            mx_lo = fmaxf(mx_lo, fmaxf(s[nt][0], s[nt][1]));
            mx_hi = fmaxf(mx_hi, fmaxf(s[nt][2], s[nt][3]));
        }
        mx_lo = fmaxf(mx_lo, __shfl_xor_sync(0xffffffffu, mx_lo, 1));
        mx_lo = fmaxf(mx_lo, __shfl_xor_sync(0xffffffffu, mx_lo, 2));
        mx_hi = fmaxf(mx_hi, __shfl_xor_sync(0xffffffffu, mx_hi, 1));
        mx_hi = fmaxf(mx_hi, __shfl_xor_sync(0xffffffffu, mx_hi, 2));

        float mn_lo = fmaxf(m_lo, mx_lo), mn_hi = fmaxf(m_hi, mx_hi);
        float al_lo = __expf(m_lo - mn_lo), al_hi = __expf(m_hi - mn_hi);
        m_lo = mn_lo; m_hi = mn_hi;

        float sa_lo = 0.f, sa_hi = 0.f;
#pragma unroll
        for (int nt = 0; nt < 16; nt++) {
            s[nt][0] = __expf(s[nt][0] - mn_lo);
            s[nt][1] = __expf(s[nt][1] - mn_lo);
            s[nt][2] = __expf(s[nt][2] - mn_hi);
            s[nt][3] = __expf(s[nt][3] - mn_hi);
            sa_lo += s[nt][0] + s[nt][1];
            sa_hi += s[nt][2] + s[nt][3];
        }
        sa_lo += __shfl_xor_sync(0xffffffffu, sa_lo, 1);
        sa_lo += __shfl_xor_sync(0xffffffffu, sa_lo, 2);
        sa_hi += __shfl_xor_sync(0xffffffffu, sa_hi, 1);
        sa_hi += __shfl_xor_sync(0xffffffffu, sa_hi, 2);
        l_lo = l_lo * al_lo + sa_lo;
        l_hi = l_hi * al_hi + sa_hi;

#pragma unroll
        for (int nt = 0; nt < 16; nt++) {
            o[nt][0] *= al_lo; o[nt][1] *= al_lo;
            o[nt][2] *= al_hi; o[nt][3] *= al_hi;
        }
        uint32_t pa[8][4];
#pragma unroll
        for (int kt = 0; kt < 8; kt++) {
            pa[kt][0] = h2pack(s[2 * kt][0], s[2 * kt][1]);
            pa[kt][1] = h2pack(s[2 * kt][2], s[2 * kt][3]);
            pa[kt][2] = h2pack(s[2 * kt + 1][0], s[2 * kt + 1][1]);
            pa[kt][3] = h2pack(s[2 * kt + 1][2], s[2 * kt + 1][3]);
        }

        // O += P @ V
#pragma unroll
        for (int ntp = 0; ntp < 8; ntp++) {
#pragma unroll
            for (int kt = 0; kt < 8; kt++) {
                uint32_t b0, b1, b2, b3;
                LDSM4(b0, b1, b2, b3, bfrag_addr(vb, lane, ntp * 16, kt * 16, QSTR));
                MMA16816(o[2 * ntp],     pa[kt], b0, b1);
                MMA16816(o[2 * ntp + 1], pa[kt], b2, b3);
            }
        }
        __syncthreads();
        if (j + 2 < nch) issue(j + 2, buf);
    }

    // epilogue
    const float inv_lo = 1.0f / l_lo, inv_hi = 1.0f / l_hi;
    const size_t rA = (size_t)(b * TSEQ + qm0 + rowl) * N_EMBD + h * HD + (lane & 3) * 2;
    const size_t rB = rA + 8 * N_EMBD;
#pragma unroll
    for (int nt = 0; nt < 16; nt++) {
        *(float2*)&out[rA + nt * 8] = make_float2(o[nt][0] * inv_lo, o[nt][1] * inv_lo);
        *(float2*)&out[rB + nt * 8] = make_float2(o[nt][2] * inv_hi, o[nt][3] * inv_hi);
    }
}

// ---------------------------------------------------------------------------
extern "C" void kernel_launch(void* const* d_in, const int* in_sizes, int n_in,
                              void* d_out, int out_size) {
    const float* x    = (const float*)d_in[0];
    const float* w_kv = (const float*)d_in[1];
    const float* w_q  = (const float*)d_in[2];
    float* out = (float*)d_out;

    cudaFuncSetAttribute(gemm_tc, cudaFuncAttributeMaxDynamicSharedMemorySize, GEMM_SMEM);
    cudaFuncSetAttribute(attn_tc, cudaFuncAttributeMaxDynamicSharedMemorySize, ATT_SMEM);

    convert_inputs<<<512, 256>>>(x, w_kv, w_q);
    dim3 g1(NTOT / 128, MTOT / 256);        // (18, 16)
    gemm_tc<<<g1, 256, GEMM_SMEM>>>();
    dim3 g2(TSEQ / 128, BATCH * NHEAD);     // (16, 32)
    attn_tc<<<g2, 256, ATT_SMEM>>>(out);
}

// round 7
// speedup vs baseline: 7.9882x; 1.0353x over previous
#include <cuda_runtime.h>
#include <cuda_fp16.h>
#include <cstdint>

#define N_EMBD 2048
#define NHEAD  16
#define HD     128
#define BATCH  2
#define TSEQ   2048
#define MTOT   (BATCH * TSEQ)
#define KDIM   N_EMBD
#define NTOT   2304
#define QSCALE 0.08838834764831845f

__device__ __half g_xh[MTOT * KDIM];
__device__ __half g_wh[NTOT * KDIM];
__device__ __half g_qh[MTOT * N_EMBD];
__device__ __half g_kh[MTOT * HD];
__device__ __half g_vt[BATCH * HD * TSEQ];

// ---------------- helpers ----------------
__device__ __forceinline__ uint32_t smem_u32(const void* p) {
    uint32_t a;
    asm("{ .reg .u64 t; cvta.to.shared.u64 t, %1; cvt.u32.u64 %0, t; }" : "=r"(a) : "l"(p));
    return a;
}
#define CP16(sm, gm)  asm volatile("cp.async.cg.shared.global [%0], [%1], 16;" :: "r"(sm), "l"(gm))
#define CP_COMMIT()   asm volatile("cp.async.commit_group;" ::: "memory")
#define CP_WAIT0()    asm volatile("cp.async.wait_group 0;" ::: "memory")
#define CP_WAIT1()    asm volatile("cp.async.wait_group 1;" ::: "memory")

#define LDSM4(r0, r1, r2, r3, a) \
    asm volatile("ldmatrix.sync.aligned.m8n8.x4.shared.b16 {%0,%1,%2,%3}, [%4];" \
                 : "=r"(r0), "=r"(r1), "=r"(r2), "=r"(r3) : "r"(a))
#define MMA16816(c, a, b0, b1) \
    asm volatile("mma.sync.aligned.m16n8k16.row.col.f32.f16.f16.f32 " \
                 "{%0,%1,%2,%3}, {%4,%5,%6,%7}, {%8,%9}, {%0,%1,%2,%3};" \
                 : "+f"((c)[0]), "+f"((c)[1]), "+f"((c)[2]), "+f"((c)[3]) \
                 : "r"((a)[0]), "r"((a)[1]), "r"((a)[2]), "r"((a)[3]), "r"(b0), "r"(b1))

__device__ __forceinline__ uint32_t h2pack(float a, float b) {
    __half2 h = __floats2half2_rn(a, b);
    return *(uint32_t*)&h;
}
// B-operand ldmatrix x4: covers n16 x k16 (two n8k16 fragments).
__device__ __forceinline__ uint32_t bfrag_addr(uint32_t base, int lane, int nbase,
                                               int kcol, int STR) {
    int row = nbase + ((lane >> 4) << 3) + (lane & 7);
    int col = kcol + ((lane >> 3) & 1) * 8;
    return base + (uint32_t)(row * STR + col) * 2u;
}

// ---------------- kernel 0: fp32 -> fp16 ----------------
__global__ void convert_inputs(const float* __restrict__ x,
                               const float* __restrict__ wkv,
                               const float* __restrict__ wq) {
    const int stride = gridDim.x * blockDim.x;
    const int t0 = blockIdx.x * blockDim.x + threadIdx.x;
    for (int i = t0; i < MTOT * KDIM / 4; i += stride) {
        float4 v = ((const float4*)x)[i];
        *(uint2*)&g_xh[4 * i] = make_uint2(h2pack(v.x, v.y), h2pack(v.z, v.w));
    }
    for (int i = t0; i < 256 * KDIM / 4; i += stride) {
        float4 v = ((const float4*)wkv)[i];
        *(uint2*)&g_wh[4 * i] = make_uint2(h2pack(v.x, v.y), h2pack(v.z, v.w));
    }
    for (int i = t0; i < N_EMBD * KDIM / 4; i += stride) {
        float4 v = ((const float4*)wq)[i];
        *(uint2*)&g_wh[256 * KDIM + 4 * i] = make_uint2(h2pack(v.x, v.y), h2pack(v.z, v.w));
    }
}

// ---------------- kernel 1: projection GEMM, 256x128x32, 3-stage ----------------
#define ASTR 40                          // halves per smem row (80B)
#define ATILE (256 * ASTR)
#define BTILE (128 * ASTR)
#define GEMM_SMEM (3 * (ATILE + BTILE) * 2)

__global__ __launch_bounds__(256, 1)
void gemm_tc() {
    extern __shared__ __half sm[];
    const uint32_t sbA = smem_u32(sm);
    const uint32_t sbB = sbA + 3 * ATILE * 2;

    const int tid = threadIdx.x, wid = tid >> 5, lane = tid & 31;
    const int n0 = blockIdx.x * 128, m0 = blockIdx.y * 256;
    const int wm = (wid & 3) * 64, wn = (wid >> 2) * 64;

    const __half* Ag = g_xh + (size_t)m0 * KDIM;
    const __half* Bg = g_wh + (size_t)n0 * KDIM;

    auto issue = [&](int g) {
        const uint32_t boA = (uint32_t)(g % 3) * ATILE * 2;
        const uint32_t boB = (uint32_t)(g % 3) * BTILE * 2;
#pragma unroll
        for (int i = 0; i < 4; i++) {                     // A: 256 rows x 4 chunks
            int idx = tid + 256 * i, r = idx >> 2, c = idx & 3;
            CP16(sbA + boA + (uint32_t)(r * ASTR + c * 8) * 2,
                 Ag + (size_t)r * KDIM + g * 32 + c * 8);
        }
#pragma unroll
        for (int i = 0; i < 2; i++) {                     // B: 128 rows x 4 chunks
            int idx = tid + 256 * i, r = idx >> 2, c = idx & 3;
            CP16(sbB + boB + (uint32_t)(r * ASTR + c * 8) * 2,
                 Bg + (size_t)r * KDIM + g * 32 + c * 8);
        }
        CP_COMMIT();
    };

    float acc[4][8][4];
#pragma unroll
    for (int mt = 0; mt < 4; mt++)
#pragma unroll
        for (int nt = 0; nt < 8; nt++)
#pragma unroll
            for (int e = 0; e < 4; e++) acc[mt][nt][e] = 0.f;

    issue(0);
    issue(1);

    const int NIT = KDIM / 32;                            // 64
    for (int j = 0; j < NIT; j++) {
        if (j + 1 < NIT) CP_WAIT1(); else CP_WAIT0();
        __syncthreads();
        if (j + 2 < NIT) issue(j + 2);
        const uint32_t boA = (uint32_t)(j % 3) * ATILE * 2;
        const uint32_t boB = (uint32_t)(j % 3) * BTILE * 2;
#pragma unroll
        for (int ks = 0; ks < 2; ks++) {
            uint32_t af[4][4];
#pragma unroll
            for (int mt = 0; mt < 4; mt++) {
                uint32_t a = sbA + boA +
                    (uint32_t)((wm + mt * 16 + (lane & 15)) * ASTR + ks * 16 + (lane >> 4) * 8) * 2;
                LDSM4(af[mt][0], af[mt][1], af[mt][2], af[mt][3], a);
            }
#pragma unroll
            for (int ntp = 0; ntp < 4; ntp++) {
                uint32_t b0, b1, b2, b3;
                LDSM4(b0, b1, b2, b3,
                      bfrag_addr(sbB + boB, lane, wn + ntp * 16, ks * 16, ASTR));
#pragma unroll
                for (int mt = 0; mt < 4; mt++) {
                    MMA16816(acc[mt][2 * ntp],     af[mt], b0, b1);
                    MMA16816(acc[mt][2 * ntp + 1], af[mt], b2, b3);
                }
            }
        }
    }

    // epilogue: bx==0 -> K, bx==1 -> V(transposed), else Q (scaled)
    const int role = (blockIdx.x == 0) ? 0 : (blockIdx.x == 1) ? 1 : 2;
    const int r0 = lane >> 2, c0 = (lane & 3) * 2;
#pragma unroll
    for (int mt = 0; mt < 4; mt++) {
#pragma unroll
        for (int nt = 0; nt < 8; nt++) {
            int tokA = m0 + wm + mt * 16 + r0;
            int col = wn + nt * 8 + c0;
            float* c = acc[mt][nt];
            if (role == 0) {
                *(uint32_t*)&g_kh[(size_t)tokA * HD + col] = h2pack(c[0], c[1]);
                *(uint32_t*)&g_kh[(size_t)(tokA + 8) * HD + col] = h2pack(c[2], c[3]);
            } else if (role == 2) {
                size_t base = (size_t)tokA * N_EMBD + (n0 - 256) + col;
                *(uint32_t*)&g_qh[base] = h2pack(c[0] * QSCALE, c[1] * QSCALE);
                *(uint32_t*)&g_qh[base + 8 * N_EMBD] = h2pack(c[2] * QSCALE, c[3] * QSCALE);
            } else {
                int bA = tokA >> 11, tl = tokA & 2047;
                int bB = (tokA + 8) >> 11, tl2 = (tokA + 8) & 2047;
                g_vt[(size_t)(bA * HD + col) * TSEQ + tl] = __float2half_rn(c[0]);
                g_vt[(size_t)(bA * HD + col + 1) * TSEQ + tl] = __float2half_rn(c[1]);
                g_vt[(size_t)(bB * HD + col) * TSEQ + tl2] = __float2half_rn(c[2]);
                g_vt[(size_t)(bB * HD + col + 1) * TSEQ + tl2] = __float2half_rn(c[3]);
            }
        }
    }
}

// ---------------- kernel 2: flash attention, BM=BN=128, 6-tile ring ----------------
#define QSTR 136                          // halves per row
#define TBUF (128 * QSTR)                 // one 128x128 tile (halves)
#define ATT_SMEM (6 * TBUF * 2)           // 208,896 B

__global__ __launch_bounds__(256, 1)
void attn_tc(float* __restrict__ out) {
    extern __shared__ __half sm[];
    const uint32_t sb = smem_u32(sm);

    const int tid = threadIdx.x, wid = tid >> 5, lane = tid & 31;
    const int qt = (int)gridDim.x - 1 - (int)blockIdx.x;   // big tiles first
    const int qm0 = qt * 128;
    const int b = blockIdx.y >> 4, h = blockIdx.y & 15;

    const __half* Qg = g_qh + (size_t)(b * TSEQ + qm0) * N_EMBD + h * HD;
    const __half* Kg = g_kh + (size_t)b * TSEQ * HD;
    const __half* Vg = g_vt + (size_t)b * HD * TSEQ;

    // tile(i) byte base
    auto tile = [&](int i) -> uint32_t { return sb + (uint32_t)i * TBUF * 2u; };

    // K chunk j -> tile (2j)%6, V^T chunk j -> tile (2j+1)%6
    auto issue = [&](int j) {
        const uint32_t kb = tile((2 * j) % 6), vb = tile((2 * j + 1) % 6);
#pragma unroll
        for (int i = 0; i < 8; i++) {
            int id = tid + 256 * i, r = id >> 4, c = id & 15;
            CP16(kb + (uint32_t)(r * QSTR + c * 8) * 2,
                 Kg + (size_t)(j * 128 + r) * HD + c * 8);
        }
#pragma unroll
        for (int i = 0; i < 8; i++) {
            int id = tid + 256 * i, r = id >> 4, c = id & 15;
            CP16(vb + (uint32_t)(r * QSTR + c * 8) * 2,
                 Vg + (size_t)r * TSEQ + j * 128 + c * 8);
        }
        CP_COMMIT();
    };

    // Q staged in tile 4 (recycled into the ring from chunk 2 on)
#pragma unroll
    for (int i = 0; i < 8; i++) {
        int id = tid + 256 * i, r = id >> 4, c = id & 15;
        *(uint4*)&sm[4 * TBUF + r * QSTR + c * 8] =
            *(const uint4*)(Qg + (size_t)r * N_EMBD + c * 8);
    }

    const int nch = qt + 1;
    issue(0);
    if (nch > 1) issue(1);
    __syncthreads();                                       // Q visible

    // Q fragments register-resident
    uint32_t qa[8][4];
#pragma unroll
    for (int kt = 0; kt < 8; kt++) {
        uint32_t a = tile(4) +
            (uint32_t)((wid * 16 + (lane & 15)) * QSTR + kt * 16 + (lane >> 4) * 8) * 2;
        LDSM4(qa[kt][0], qa[kt][1], qa[kt][2], qa[kt][3], a);
    }

    float o[16][4];
#pragma unroll
    for (int nt = 0; nt < 16; nt++)
#pragma unroll
        for (int e = 0; e < 4; e++) o[nt][e] = 0.f;
    float m_lo = -1e30f, m_hi = -1e30f, l_lo = 0.f, l_hi = 0.f;

    const int rowl = wid * 16 + (lane >> 2);               // local row (and +8)

    for (int j = 0; j < nch; j++) {
        if (j + 1 < nch) CP_WAIT1(); else CP_WAIT0();
        __syncthreads();                                   // single barrier per chunk
        if (j + 2 < nch) issue(j + 2);
        const uint32_t kb = tile((2 * j) % 6), vb = tile((2 * j + 1) % 6);

        // S = Q @ K^T  (128 keys)
        float s[16][4];
#pragma unroll
        for (int ntp = 0; ntp < 8; ntp++) {
            s[2 * ntp][0] = s[2 * ntp][1] = s[2 * ntp][2] = s[2 * ntp][3] = 0.f;
            s[2 * ntp + 1][0] = s[2 * ntp + 1][1] = s[2 * ntp + 1][2] = s[2 * ntp + 1][3] = 0.f;
#pragma unroll
            for (int kt = 0; kt < 8; kt++) {
                uint32_t b0, b1, b2, b3;
                LDSM4(b0, b1, b2, b3, bfrag_addr(kb, lane, ntp * 16, kt * 16, QSTR));
                MMA16816(s[2 * ntp],     qa[kt], b0, b1);
                MMA16816(s[2 * ntp + 1], qa[kt], b2, b3);
            }
        }

        // causal mask (diagonal chunk only)
        if (j == qt) {
#pragma unroll
            for (int nt = 0; nt < 16; nt++) {
                int cl = nt * 8 + (lane & 3) * 2;
                if (cl > rowl)         s[nt][0] = -1e30f;
                if (cl + 1 > rowl)     s[nt][1] = -1e30f;
                if (cl > rowl + 8)     s[nt][2] = -1e30f;
                if (cl + 1 > rowl + 8) s[nt][3] = -1e30f;
            }
        }

        // online softmax
        float mx_lo = -1e30f, mx_hi = -1e30f;
#pragma unroll
        for (int nt = 0; nt < 16; nt++) {
            mx_lo = fmaxf(mx_lo, fmaxf(s[nt][0], s[nt][1]));
            mx_hi = fmaxf(mx_hi, fmaxf(s[nt][2], s[nt][3]));
        }
        mx_lo = fmaxf(mx_lo, __shfl_xor_sync(0xffffffffu, mx_lo, 1));
        mx_lo = fmaxf(mx_lo, __shfl_xor_sync(0xffffffffu, mx_lo, 2));
        mx_hi = fmaxf(mx_hi, __shfl_xor_sync(0xffffffffu, mx_hi, 1));
        mx_hi = fmaxf(mx_hi, __shfl_xor_sync(0xffffffffu, mx_hi, 2));

        float mn_lo = fmaxf(m_lo, mx_lo), mn_hi = fmaxf(m_hi, mx_hi);
        float al_lo = __expf(m_lo - mn_lo), al_hi = __expf(m_hi - mn_hi);
        m_lo = mn_lo; m_hi = mn_hi;

        float sa_lo = 0.f, sa_hi = 0.f;
#pragma unroll
        for (int nt = 0; nt < 16; nt++) {
            s[nt][0] = __expf(s[nt][0] - mn_lo);
            s[nt][1] = __expf(s[nt][1] - mn_lo);
            s[nt][2] = __expf(s[nt][2] - mn_hi);
            s[nt][3] = __expf(s[nt][3] - mn_hi);
            sa_lo += s[nt][0] + s[nt][1];
            sa_hi += s[nt][2] + s[nt][3];
        }
        sa_lo += __shfl_xor_sync(0xffffffffu, sa_lo, 1);
        sa_lo += __shfl_xor_sync(0xffffffffu, sa_lo, 2);
        sa_hi += __shfl_xor_sync(0xffffffffu, sa_hi, 1);
        sa_hi += __shfl_xor_sync(0xffffffffu, sa_hi, 2);
        l_lo = l_lo * al_lo + sa_lo;
        l_hi = l_hi * al_hi + sa_hi;

#pragma unroll
        for (int nt = 0; nt < 16; nt++) {
            o[nt][0] *= al_lo; o[nt][1] *= al_lo;
            o[nt][2] *= al_hi; o[nt][3] *= al_hi;
        }
        uint32_t pa[8][4];
#pragma unroll
        for (int kt = 0; kt < 8; kt++) {
            pa[kt][0] = h2pack(s[2 * kt][0], s[2 * kt][1]);
            pa[kt][1] = h2pack(s[2 * kt][2], s[2 * kt][3]);
            pa[kt][2] = h2pack(s[2 * kt + 1][0], s[2 * kt + 1][1]);
            pa[kt][3] = h2pack(s[2 * kt + 1][2], s[2 * kt + 1][3]);
        }

        // O += P @ V
#pragma unroll
        for (int ntp = 0; ntp < 8; ntp++) {
#pragma unroll
            for (int kt = 0; kt < 8; kt++) {
                uint32_t b0, b1, b2, b3;
                LDSM4(b0, b1, b2, b3, bfrag_addr(vb, lane, ntp * 16, kt * 16, QSTR));
                MMA16816(o[2 * ntp],     pa[kt], b0, b1);
                MMA16816(o[2 * ntp + 1], pa[kt], b2, b3);
            }
        }
    }

    // epilogue
    const float inv_lo = 1.0f / l_lo, inv_hi = 1.0f / l_hi;
    const size_t rA = (size_t)(b * TSEQ + qm0 + rowl) * N_EMBD + h * HD + (lane & 3) * 2;
    const size_t rB = rA + 8 * N_EMBD;
#pragma unroll
    for (int nt = 0; nt < 16; nt++) {
        *(float2*)&out[rA + nt * 8] = make_float2(o[nt][0] * inv_lo, o[nt][1] * inv_lo);
        *(float2*)&out[rB + nt * 8] = make_float2(o[nt][2] * inv_hi, o[nt][3] * inv_hi);
    }
}

// ---------------------------------------------------------------------------
extern "C" void kernel_launch(void* const* d_in, const int* in_sizes, int n_in,
                              void* d_out, int out_size) {
    const float* x    = (const float*)d_in[0];
    const float* w_kv = (const float*)d_in[1];
    const float* w_q  = (const float*)d_in[2];
    float* out = (float*)d_out;

    cudaFuncSetAttribute(gemm_tc, cudaFuncAttributeMaxDynamicSharedMemorySize, GEMM_SMEM);
    cudaFuncSetAttribute(attn_tc, cudaFuncAttributeMaxDynamicSharedMemorySize, ATT_SMEM);

    convert_inputs<<<1024, 256>>>(x, w_kv, w_q);
    dim3 g1(NTOT / 128, MTOT / 256);        // (18, 16)
    gemm_tc<<<g1, 256, GEMM_SMEM>>>();
    dim3 g2(TSEQ / 128, BATCH * NHEAD);     // (16, 32)
    attn_tc<<<g2, 256, ATT_SMEM>>>(out);
}